// round 1
// baseline (speedup 1.0000x reference)
#include <cuda_runtime.h>

// ROIAlign: features (B=4, C=64, H=38, W=38) fp32, rois (B, Nb=2904, 4) fp32
// -> out (B*Nb, C, 7, 7) fp32.
//
// Strategy: one block per ROI. blockDim = (49, 8) = 392 threads.
//   threadIdx.x = p in [0,49): fixed output pixel (oy,ox); bilinear weights and
//                 clamped texel offsets computed ONCE into registers.
//   threadIdx.y + 8*i = channel. Store address = linear_tid + 392*i per
//                 iteration -> fully coalesced warp stores.
// Features (1.48 MB) are L2-resident; output writes (145.7 MB) bound the kernel.

#define FH 38
#define FW 38
#define FC 64
#define OS 7
#define PLANE (FH * FW)          // 1444
#define PER_ROI (FC * OS * OS)   // 3136

__global__ __launch_bounds__(392, 4)
void roialign_kernel(const float* __restrict__ feat,
                     const float* __restrict__ rois,
                     float* __restrict__ out,
                     int nb_per_batch)
{
    const int n = blockIdx.x;                 // roi index
    const int p = threadIdx.x;                // 0..48 output pixel
    const int b = n / nb_per_batch;           // batch index

    // ROI box (16B-aligned vector load; broadcast across block via L1)
    const float4 r = __ldg(reinterpret_cast<const float4*>(rois) + n);
    const float rw = fmaxf(r.z - r.x, 1.0f);
    const float rh = fmaxf(r.w - r.y, 1.0f);

    const int ox = p % OS;
    const int oy = p / OS;

    const float x = fmaf((float)ox * (1.0f / 6.0f), rw, r.x);
    const float y = fmaf((float)oy * (1.0f / 6.0f), rh, r.y);

    const float x0f = floorf(x);
    const float y0f = floorf(y);
    const float fx = x - x0f;
    const float fy = y - y0f;

    const int x0 = (int)x0f;
    const int y0 = (int)y0f;
    const int x1 = x0 + 1;
    const int y1 = y0 + 1;

    const bool vx0 = (x0 >= 0) && (x0 <= FW - 1);
    const bool vx1 = (x1 >= 0) && (x1 <= FW - 1);
    const bool vy0 = (y0 >= 0) && (y0 <= FH - 1);
    const bool vy1 = (y1 >= 0) && (y1 <= FH - 1);

    const int xi0 = min(max(x0, 0), FW - 1);
    const int xi1 = min(max(x1, 0), FW - 1);
    const int yi0 = min(max(y0, 0), FH - 1);
    const int yi1 = min(max(y1, 0), FH - 1);

    const float wx0 = 1.0f - fx, wx1 = fx;
    const float wy0 = 1.0f - fy, wy1 = fy;

    // weights zeroed when the UNCLAMPED corner is out of bounds (matches ref)
    const float w00 = (vx0 && vy0) ? wx0 * wy0 : 0.0f;
    const float w01 = (vx1 && vy0) ? wx1 * wy0 : 0.0f;
    const float w10 = (vx0 && vy1) ? wx0 * wy1 : 0.0f;
    const float w11 = (vx1 && vy1) ? wx1 * wy1 : 0.0f;

    const int o00 = yi0 * FW + xi0;
    const int o01 = yi0 * FW + xi1;
    const int o10 = yi1 * FW + xi0;
    const int o11 = yi1 * FW + xi1;

    const float* __restrict__ fb = feat + (size_t)b * (FC * PLANE);
    float* __restrict__ ob = out + (size_t)n * PER_ROI + p;

#pragma unroll
    for (int i = 0; i < 8; i++) {
        const int c = threadIdx.y + 8 * i;
        const float* __restrict__ fc = fb + c * PLANE;
        float v = w00 * __ldg(fc + o00);
        v = fmaf(w01, __ldg(fc + o01), v);
        v = fmaf(w10, __ldg(fc + o10), v);
        v = fmaf(w11, __ldg(fc + o11), v);
        ob[c * (OS * OS)] = v;
    }
}

extern "C" void kernel_launch(void* const* d_in, const int* in_sizes, int n_in,
                              void* d_out, int out_size)
{
    const float* feat = (const float*)d_in[0];   // (B, 64, 38, 38)
    const float* rois = (const float*)d_in[1];   // (B, Nb, 4)
    float* out = (float*)d_out;

    const int B = in_sizes[0] / (FC * FH * FW);  // 4
    const int n_roi = in_sizes[1] / 4;           // 11616
    const int nb = n_roi / B;                    // 2904

    dim3 block(49, 8);
    roialign_kernel<<<n_roi, block>>>(feat, rois, out, nb);
}